// round 2
// baseline (speedup 1.0000x reference)
#include <cuda_runtime.h>
#include <math_constants.h>

// Problem dims
#define BATCH 64
#define DIM   768
#define MEM   2048
#define NCLS  1000

// Scratch (allocation-free): q = x@W_K, t = q@W_Q, logits accumulator
__device__ float g_q[BATCH * DIM];
__device__ float g_t[BATCH * DIM];
__device__ float g_logits[BATCH * NCLS];
__device__ int   g_lab_is64;   // 1 if labels are int64, 0 if int32

// ---------------------------------------------------------------------------
// Zero scratch + detect label dtype.
// grid 250 x 256 covers max(64*1000=64000, 64*768=49152).
// Detection: view labels as int32 words. If the buffer is int64 (values in
// [0,1000), nonneg), every odd word (high half, little-endian) is 0. If it is
// int32, odd words are labels themselves — P(32 consecutive are all 0) ~ 0.
// ---------------------------------------------------------------------------
__global__ void zero_scratch(const int* __restrict__ lab32) {
    int i = blockIdx.x * blockDim.x + threadIdx.x;
    if (i < BATCH * DIM) { g_q[i] = 0.0f; g_t[i] = 0.0f; }
    if (i < BATCH * NCLS) g_logits[i] = 0.0f;
    if (blockIdx.x == 0 && threadIdx.x == 0) {
        int any = 0;
        #pragma unroll
        for (int k = 0; k < 32; k++) any |= lab32[2 * k + 1];
        g_lab_is64 = (any == 0) ? 1 : 0;
    }
}

// ---------------------------------------------------------------------------
// GEMM stage: C[64,768] += A[64,768] @ W[768,768]  (row-major, split-K)
// grid = (6 j-tiles of 128, 24 k-chunks of 32), block = 256 threads.
// Thread covers 4 consecutive j (float4 W load) x 8 consecutive b (smem
// broadcast) -> 32 accumulators, 8x W reuse, fully coalesced.
// stage==0:  A = x (param),  C = g_q   (W = W_K)
// stage==1:  A = g_q,        C = g_t   (W = W_Q)
// ---------------------------------------------------------------------------
#define KC 32
__global__ void gemm_stage(const float* __restrict__ Aext,
                           const float* __restrict__ W,
                           int stage) {
    const float* A = (stage == 0) ? Aext : g_q;
    float* Cc      = (stage == 0) ? g_q  : g_t;

    __shared__ float xs[KC][BATCH + 1];  // +1 pad: conflict-free transposed store

    const int k0 = blockIdx.y * KC;

    // Cooperative load of A chunk, transposed: xs[d][b] = A[b, k0+d]
    for (int i = threadIdx.x; i < BATCH * KC; i += 256) {
        int b = i >> 5;         // i / 32
        int d = i & (KC - 1);   // i % 32
        xs[d][b] = A[b * DIM + k0 + d];
    }
    __syncthreads();

    const int jv = threadIdx.x & 31;   // 32 j-vec positions
    const int bg = threadIdx.x >> 5;   // 8 b-groups of 8
    const int j  = blockIdx.x * 128 + jv * 4;

    float acc[8][4];
    #pragma unroll
    for (int bb = 0; bb < 8; bb++)
        #pragma unroll
        for (int jj = 0; jj < 4; jj++) acc[bb][jj] = 0.0f;

    #pragma unroll
    for (int d = 0; d < KC; d++) {
        const float4 w = *(const float4*)&W[(size_t)(k0 + d) * DIM + j];
        #pragma unroll
        for (int bb = 0; bb < 8; bb++) {
            const float xv = xs[d][bg * 8 + bb];  // warp-uniform -> broadcast
            acc[bb][0] = fmaf(xv, w.x, acc[bb][0]);
            acc[bb][1] = fmaf(xv, w.y, acc[bb][1]);
            acc[bb][2] = fmaf(xv, w.z, acc[bb][2]);
            acc[bb][3] = fmaf(xv, w.w, acc[bb][3]);
        }
    }

    #pragma unroll
    for (int bb = 0; bb < 8; bb++) {
        const int b = bg * 8 + bb;
        atomicAdd(&Cc[b * DIM + j + 0], acc[bb][0]);
        atomicAdd(&Cc[b * DIM + j + 1], acc[bb][1]);
        atomicAdd(&Cc[b * DIM + j + 2], acc[bb][2]);
        atomicAdd(&Cc[b * DIM + j + 3], acc[bb][3]);
    }
}

// ---------------------------------------------------------------------------
// Dominant kernel: scores[b,m] = sum_e t[b,e]*mem[b,e,m]; leaky-relu; scatter
// into g_logits[b, label]. Streams 402 MB of mem exactly once (HBM-bound).
// grid = (MEM/512, BATCH) = (4, 64) = 256 blocks; block = 128 threads.
// Each thread: 4 consecutive m via float4 streaming loads (__ldcs).
// ---------------------------------------------------------------------------
__global__ void score_scatter(const float* __restrict__ mem,
                              const int* __restrict__ lab32) {
    const int b = blockIdx.y;

    __shared__ float ts[DIM];
    for (int i = threadIdx.x; i < DIM; i += 128) ts[i] = g_t[b * DIM + i];
    __syncthreads();

    const int m = blockIdx.x * 512 + threadIdx.x * 4;
    const float4* mp = (const float4*)(mem + (size_t)b * DIM * MEM + m);

    float ax = 0.f, ay = 0.f, az = 0.f, aw = 0.f;
    #pragma unroll 4
    for (int e = 0; e < DIM; e++) {
        const float4 v = __ldcs(&mp[(size_t)e * (MEM / 4)]);
        const float w = ts[e];  // warp-uniform broadcast
        ax = fmaf(w, v.x, ax);
        ay = fmaf(w, v.y, ay);
        az = fmaf(w, v.z, az);
        aw = fmaf(w, v.w, aw);
    }

    const int is64 = g_lab_is64;
    float s[4] = {ax, ay, az, aw};
    #pragma unroll
    for (int k = 0; k < 4; k++) {
        const float sv = (s[k] >= 0.0f) ? s[k] : 0.01f * s[k];
        const size_t idx = (size_t)b * MEM + m + k;
        int lab = is64 ? lab32[2 * idx]    // low word of little-endian int64
                       : lab32[idx];       // plain int32
        lab = min(max(lab, 0), NCLS - 1);  // never OOB, even if assumptions break
        atomicAdd(&g_logits[b * NCLS + lab], sv);
    }
}

// ---------------------------------------------------------------------------
// Row softmax: out[b, :] = softmax(g_logits[b, :]).  64 blocks x 256 threads.
// ---------------------------------------------------------------------------
__global__ void softmax_rows(float* __restrict__ out) {
    const int b = blockIdx.x;
    const int tid = threadIdx.x;

    __shared__ float buf[NCLS];
    __shared__ float red[32];

    // --- max ---
    float mx = -CUDART_INF_F;
    for (int i = tid; i < NCLS; i += 256) mx = fmaxf(mx, g_logits[b * NCLS + i]);
    #pragma unroll
    for (int o = 16; o > 0; o >>= 1) mx = fmaxf(mx, __shfl_xor_sync(0xffffffffu, mx, o));
    if ((tid & 31) == 0) red[tid >> 5] = mx;
    __syncthreads();
    if (tid < 32) {
        float v = (tid < 8) ? red[tid] : -CUDART_INF_F;
        #pragma unroll
        for (int o = 4; o > 0; o >>= 1) v = fmaxf(v, __shfl_xor_sync(0xffffffffu, v, o));
        if (tid == 0) red[0] = v;
    }
    __syncthreads();
    mx = red[0];
    __syncthreads();  // everyone has mx in a register before red is reused

    // --- exp + sum ---
    float sum = 0.0f;
    for (int i = tid; i < NCLS; i += 256) {
        const float e = __expf(g_logits[b * NCLS + i] - mx);
        buf[i] = e;
        sum += e;
    }
    #pragma unroll
    for (int o = 16; o > 0; o >>= 1) sum += __shfl_xor_sync(0xffffffffu, sum, o);
    if ((tid & 31) == 0) red[tid >> 5] = sum;
    __syncthreads();
    if (tid < 32) {
        float v = (tid < 8) ? red[tid] : 0.0f;
        #pragma unroll
        for (int o = 4; o > 0; o >>= 1) v += __shfl_xor_sync(0xffffffffu, v, o);
        if (tid == 0) red[0] = v;
    }
    __syncthreads();
    const float inv = 1.0f / red[0];

    for (int i = tid; i < NCLS; i += 256) out[b * NCLS + i] = buf[i] * inv;
}

// ---------------------------------------------------------------------------
// Launch: zero -> q = x@W_K -> t = q@W_Q -> score+scatter -> softmax
// Inputs mapped by element count (robust to metadata ordering):
//   x: 64*768=49152, mem: 64*768*2048=100663296, labels: 64*2048=131072,
//   W_Q / W_K: 768*768=589824 each (relative order preserved: W_Q first).
// Output: f32[64,1000].
// ---------------------------------------------------------------------------
extern "C" void kernel_launch(void* const* d_in, const int* in_sizes, int n_in,
                              void* d_out, int out_size) {
    const float* x   = nullptr;
    const float* mem = nullptr;
    const int* labs  = nullptr;
    const float* W_Q = nullptr;
    const float* W_K = nullptr;

    for (int i = 0; i < n_in; i++) {
        const int sz = in_sizes[i];
        if (sz == BATCH * DIM)            x    = (const float*)d_in[i];
        else if (sz == BATCH * DIM * MEM) mem  = (const float*)d_in[i];
        else if (sz == BATCH * MEM)       labs = (const int*)d_in[i];
        else if (sz == DIM * DIM) {
            if (!W_Q) W_Q = (const float*)d_in[i];
            else      W_K = (const float*)d_in[i];
        }
    }
    float* out = (float*)d_out;

    zero_scratch<<<250, 256>>>(labs);
    gemm_stage<<<dim3(DIM / 128, DIM / KC), 256>>>(x, W_K, 0);  // q = x @ W_K
    gemm_stage<<<dim3(DIM / 128, DIM / KC), 256>>>(x, W_Q, 1);  // t = q @ W_Q
    score_scatter<<<dim3(MEM / 512, BATCH), 128>>>(mem, labs);
    softmax_rows<<<BATCH, 256>>>(out);
}

// round 3
// speedup vs baseline: 1.6355x; 1.6355x over previous
#include <cuda_runtime.h>
#include <math_constants.h>

// Problem dims
#define BATCH 64
#define DIM   768
#define MEM   2048
#define NCLS  1000

#define EC 96                  // e-chunk per block (DIM/EC = 8 chunks)
#define NEC (DIM / EC)

// Scratch (allocation-free)
__device__ float g_q[BATCH * DIM];
__device__ float g_t[BATCH * DIM];
__device__ float g_scores[BATCH * MEM];
__device__ float g_logits[BATCH * NCLS];
__device__ int   g_lab_is64;   // 1 if labels are int64, 0 if int32

// ---------------------------------------------------------------------------
// Zero scratch + detect label dtype.  512 blocks x 256 covers 131072.
// Detection: if buffer is int64 (values in [0,1000)), every odd 32-bit word
// is 0; if int32, odd words are random labels (P[all 32 zero] ~ 0).
// ---------------------------------------------------------------------------
__global__ void zero_scratch(const int* __restrict__ lab32) {
    int i = blockIdx.x * blockDim.x + threadIdx.x;
    if (i < BATCH * DIM)  { g_q[i] = 0.0f; g_t[i] = 0.0f; }
    if (i < BATCH * NCLS) g_logits[i] = 0.0f;
    if (i < BATCH * MEM)  g_scores[i] = 0.0f;
    if (blockIdx.x == 0 && threadIdx.x == 0) {
        int any = 0;
        #pragma unroll
        for (int k = 0; k < 32; k++) any |= lab32[2 * k + 1];
        g_lab_is64 = (any == 0) ? 1 : 0;
    }
}

// ---------------------------------------------------------------------------
// GEMM stage: C[64,768] += A[64,768] @ W[768,768]  (row-major, split-K)
// grid = (6 j-tiles of 128, 24 k-chunks of 32), block = 256 threads.
// ---------------------------------------------------------------------------
#define KC 32
__global__ void gemm_stage(const float* __restrict__ Aext,
                           const float* __restrict__ W,
                           int stage) {
    const float* A = (stage == 0) ? Aext : g_q;
    float* Cc      = (stage == 0) ? g_q  : g_t;

    __shared__ float xs[KC][BATCH + 1];

    const int k0 = blockIdx.y * KC;

    for (int i = threadIdx.x; i < BATCH * KC; i += 256) {
        int b = i >> 5;
        int d = i & (KC - 1);
        xs[d][b] = A[b * DIM + k0 + d];
    }
    __syncthreads();

    const int jv = threadIdx.x & 31;
    const int bg = threadIdx.x >> 5;
    const int j  = blockIdx.x * 128 + jv * 4;

    float acc[8][4];
    #pragma unroll
    for (int bb = 0; bb < 8; bb++)
        #pragma unroll
        for (int jj = 0; jj < 4; jj++) acc[bb][jj] = 0.0f;

    #pragma unroll
    for (int d = 0; d < KC; d++) {
        const float4 w = *(const float4*)&W[(size_t)(k0 + d) * DIM + j];
        #pragma unroll
        for (int bb = 0; bb < 8; bb++) {
            const float xv = xs[d][bg * 8 + bb];
            acc[bb][0] = fmaf(xv, w.x, acc[bb][0]);
            acc[bb][1] = fmaf(xv, w.y, acc[bb][1]);
            acc[bb][2] = fmaf(xv, w.z, acc[bb][2]);
            acc[bb][3] = fmaf(xv, w.w, acc[bb][3]);
        }
    }

    #pragma unroll
    for (int bb = 0; bb < 8; bb++) {
        const int b = bg * 8 + bb;
        atomicAdd(&Cc[b * DIM + j + 0], acc[bb][0]);
        atomicAdd(&Cc[b * DIM + j + 1], acc[bb][1]);
        atomicAdd(&Cc[b * DIM + j + 2], acc[bb][2]);
        atomicAdd(&Cc[b * DIM + j + 3], acc[bb][3]);
    }
}

// ---------------------------------------------------------------------------
// Dominant kernel: partial scores[b,m] += sum_{e in chunk} t[b,e]*mem[b,e,m].
// Streams 402 MB of mem exactly once. Split over e for occupancy:
// grid = (MEM/1024, DIM/EC, BATCH) = (2, 8, 64) = 1024 blocks x 256 threads
// (~55 warps/SM). Each thread: 4 consecutive m via float4 streaming loads,
// EC=96 iterations, unroll 8 for MLP, then 4 spread atomicAdds (REDG).
// ---------------------------------------------------------------------------
__global__ void __launch_bounds__(256) score_partial(const float* __restrict__ mem) {
    const int b  = blockIdx.z;
    const int e0 = blockIdx.y * EC;

    __shared__ float ts[EC];
    if (threadIdx.x < EC) ts[threadIdx.x] = g_t[b * DIM + e0 + threadIdx.x];
    __syncthreads();

    const int m = blockIdx.x * 1024 + threadIdx.x * 4;
    const float4* mp = (const float4*)(mem + (size_t)b * DIM * MEM
                                           + (size_t)e0 * MEM + m);

    float ax = 0.f, ay = 0.f, az = 0.f, aw = 0.f;
    #pragma unroll 8
    for (int e = 0; e < EC; e++) {
        const float4 v = __ldcs(&mp[(size_t)e * (MEM / 4)]);
        const float w = ts[e];  // warp-uniform broadcast
        ax = fmaf(w, v.x, ax);
        ay = fmaf(w, v.y, ay);
        az = fmaf(w, v.z, az);
        aw = fmaf(w, v.w, aw);
    }

    float* sp = &g_scores[b * MEM + m];
    atomicAdd(sp + 0, ax);
    atomicAdd(sp + 1, ay);
    atomicAdd(sp + 2, az);
    atomicAdd(sp + 3, aw);
}

// ---------------------------------------------------------------------------
// Epilogue: leaky-relu(scores) scatter-added into g_logits[b, label].
// grid = 128 blocks x 256 threads over 131072 items.
// ---------------------------------------------------------------------------
__global__ void relu_scatter(const int* __restrict__ lab32) {
    const int i = blockIdx.x * blockDim.x + threadIdx.x;
    #pragma unroll
    for (int r = 0; r < 4; r++) {
        const int idx = i * 4 + r;
        if (idx >= BATCH * MEM) return;
        const int b = idx / MEM;
        const float s = g_scores[idx];
        const float sv = (s >= 0.0f) ? s : 0.01f * s;
        int lab = g_lab_is64 ? lab32[2 * idx] : lab32[idx];
        lab = min(max(lab, 0), NCLS - 1);
        atomicAdd(&g_logits[b * NCLS + lab], sv);
    }
}

// ---------------------------------------------------------------------------
// Row softmax: out[b, :] = softmax(g_logits[b, :]).  64 blocks x 256 threads.
// ---------------------------------------------------------------------------
__global__ void softmax_rows(float* __restrict__ out) {
    const int b = blockIdx.x;
    const int tid = threadIdx.x;

    __shared__ float buf[NCLS];
    __shared__ float red[32];

    float mx = -CUDART_INF_F;
    for (int i = tid; i < NCLS; i += 256) mx = fmaxf(mx, g_logits[b * NCLS + i]);
    #pragma unroll
    for (int o = 16; o > 0; o >>= 1) mx = fmaxf(mx, __shfl_xor_sync(0xffffffffu, mx, o));
    if ((tid & 31) == 0) red[tid >> 5] = mx;
    __syncthreads();
    if (tid < 32) {
        float v = (tid < 8) ? red[tid] : -CUDART_INF_F;
        #pragma unroll
        for (int o = 4; o > 0; o >>= 1) v = fmaxf(v, __shfl_xor_sync(0xffffffffu, v, o));
        if (tid == 0) red[0] = v;
    }
    __syncthreads();
    mx = red[0];
    __syncthreads();

    float sum = 0.0f;
    for (int i = tid; i < NCLS; i += 256) {
        const float e = __expf(g_logits[b * NCLS + i] - mx);
        buf[i] = e;
        sum += e;
    }
    #pragma unroll
    for (int o = 16; o > 0; o >>= 1) sum += __shfl_xor_sync(0xffffffffu, sum, o);
    if ((tid & 31) == 0) red[tid >> 5] = sum;
    __syncthreads();
    if (tid < 32) {
        float v = (tid < 8) ? red[tid] : 0.0f;
        #pragma unroll
        for (int o = 4; o > 0; o >>= 1) v += __shfl_xor_sync(0xffffffffu, v, o);
        if (tid == 0) red[0] = v;
    }
    __syncthreads();
    const float inv = 1.0f / red[0];

    for (int i = tid; i < NCLS; i += 256) out[b * NCLS + i] = buf[i] * inv;
}

// ---------------------------------------------------------------------------
// Launch: zero -> q = x@W_K -> t = q@W_Q -> score partials -> relu+scatter
//         -> softmax
// Inputs mapped by element count: x 49152, mem 100663296, labels 131072,
// W_Q / W_K 589824 each (W_Q first).
// ---------------------------------------------------------------------------
extern "C" void kernel_launch(void* const* d_in, const int* in_sizes, int n_in,
                              void* d_out, int out_size) {
    const float* x   = nullptr;
    const float* mem = nullptr;
    const int* labs  = nullptr;
    const float* W_Q = nullptr;
    const float* W_K = nullptr;

    for (int i = 0; i < n_in; i++) {
        const int sz = in_sizes[i];
        if (sz == BATCH * DIM)            x    = (const float*)d_in[i];
        else if (sz == BATCH * DIM * MEM) mem  = (const float*)d_in[i];
        else if (sz == BATCH * MEM)       labs = (const int*)d_in[i];
        else if (sz == DIM * DIM) {
            if (!W_Q) W_Q = (const float*)d_in[i];
            else      W_K = (const float*)d_in[i];
        }
    }
    float* out = (float*)d_out;

    zero_scratch<<<512, 256>>>(labs);
    gemm_stage<<<dim3(DIM / 128, DIM / KC), 256>>>(x, W_K, 0);  // q = x @ W_K
    gemm_stage<<<dim3(DIM / 128, DIM / KC), 256>>>(x, W_Q, 1);  // t = q @ W_Q
    score_partial<<<dim3(MEM / 1024, NEC, BATCH), 256>>>(mem);
    relu_scatter<<<128, 256>>>(labs);
    softmax_rows<<<BATCH, 256>>>(out);
}